// round 1
// baseline (speedup 1.0000x reference)
#include <cuda_runtime.h>

// FAVOR+ attention, fp32 baseline.
// B=4, L=4096, D=1024, H=16 heads of d=64, m=256 features.
// Pipeline: zero scratch -> global min ||k_chunk||^2 -> K-side (phi_k fused with
// kv/ksum accumulation) -> Q-side (phi_q fused with output GEMM + denom).

namespace {
constexpr int B_ = 4;
constexpr int L_ = 4096;
constexpr int D_ = 1024;
constexpr int H_ = 16;
constexpr int d_ = 64;
constexpr int M_ = 256;
constexpr int SPLIT = 8;
constexpr int RPB = L_ / SPLIT;   // 512 rows per block
constexpr int CHUNK = 16;
constexpr float SCALE = 0.17677669529663687f;  // 1024^-0.25
constexpr float CEPS = 1e-4f;
constexpr float INVSQM = 0.0625f;              // 256^-0.5
constexpr int QP_STRIDE = 260;                 // padded to dodge bank conflicts
constexpr int QSMEM_FLOATS = M_ * d_ + CHUNK * QP_STRIDE + CHUNK * d_ + M_;
constexpr int QSMEM_BYTES = QSMEM_FLOATS * 4;  // 87296
}

__device__ float g_kv[B_ * H_ * M_ * d_];   // 16 MB scratch
__device__ float g_ksum[B_ * H_ * M_];
__device__ unsigned int g_min_ss;

// ---------------------------------------------------------------------------
// Kernel 0: re-zero scratch + init min (must run every launch: graph replays)
// ---------------------------------------------------------------------------
__global__ void zero_kernel() {
    size_t tid = (size_t)blockIdx.x * blockDim.x + threadIdx.x;
    size_t stride = (size_t)gridDim.x * blockDim.x;
    constexpr size_t nkv = (size_t)B_ * H_ * M_ * d_;
    for (size_t i = tid; i < nkv; i += stride) g_kv[i] = 0.f;
    constexpr size_t nks = (size_t)B_ * H_ * M_;
    for (size_t i = tid; i < nks; i += stride) g_ksum[i] = 0.f;
    if (tid == 0) g_min_ss = 0x7F800000u;  // +inf
}

// ---------------------------------------------------------------------------
// Kernel 1: global min over all (b,h,l) of ||k_head_row||^2 (raw, unscaled).
// stab = -0.5 * SCALE^2 * min_ss  ==  max over all h of -0.5*||k*scale||^2
// ---------------------------------------------------------------------------
__global__ __launch_bounds__(256) void min_kernel(const float* __restrict__ Kp) {
    int t = threadIdx.x;
    float mn = 3.4028235e38f;
#pragma unroll
    for (int it = 0; it < 16; ++it) {
        size_t ch = (size_t)blockIdx.x * 256 + it * 16 + (t >> 4);
        float4 v4 = *reinterpret_cast<const float4*>(Kp + ch * 64 + (t & 15) * 4);
        float ss = v4.x * v4.x + v4.y * v4.y + v4.z * v4.z + v4.w * v4.w;
        ss += __shfl_xor_sync(0xffffffffu, ss, 8);
        ss += __shfl_xor_sync(0xffffffffu, ss, 4);
        ss += __shfl_xor_sync(0xffffffffu, ss, 2);
        ss += __shfl_xor_sync(0xffffffffu, ss, 1);
        mn = fminf(mn, ss);
    }
    mn = fminf(mn, __shfl_xor_sync(0xffffffffu, mn, 16));
    __shared__ float wmin[8];
    if ((t & 31) == 0) wmin[t >> 5] = mn;
    __syncthreads();
    if (t < 8) {
        float m2 = wmin[t];
        m2 = fminf(m2, __shfl_xor_sync(0xffu, m2, 4));
        m2 = fminf(m2, __shfl_xor_sync(0xffu, m2, 2));
        m2 = fminf(m2, __shfl_xor_sync(0xffu, m2, 1));
        if (t == 0) atomicMin(&g_min_ss, __float_as_uint(m2));
    }
}

// ---------------------------------------------------------------------------
// Kernel 2: K side. Thread j owns W row j (regs) and kv row j (regs).
// Per 16-row chunk: stage scaled k rows + v rows in smem (broadcast reads),
// compute proj_j per row, k' = c*(exp(h + proj - stab) + eps),
// rank-1 accumulate kv[j][:] += k' * v_row.  Atomic writeback per block.
// ---------------------------------------------------------------------------
__global__ __launch_bounds__(256, 1) void phik_kernel(
    const float* __restrict__ Kp, const float* __restrict__ Vp,
    const float* __restrict__ Wp) {
    const int j = threadIdx.x;
    const int bh = blockIdx.x;
    const int bb = bh >> 4, hh = bh & 15;
    float wj[64];
    {
        const float4* w4 = reinterpret_cast<const float4*>(Wp + j * 64);
#pragma unroll
        for (int i = 0; i < 16; ++i) {
            float4 tw = w4[i];
            wj[4 * i] = tw.x; wj[4 * i + 1] = tw.y;
            wj[4 * i + 2] = tw.z; wj[4 * i + 3] = tw.w;
        }
    }
    const float stab = -0.5f * SCALE * SCALE * __uint_as_float(g_min_ss);
    float kvacc[64];
#pragma unroll
    for (int i = 0; i < 64; ++i) kvacc[i] = 0.f;
    float ksacc = 0.f;

    __shared__ float sk[CHUNK][64];
    __shared__ float sv[CHUNK][64];
    __shared__ float sh[CHUNK];
    const int r = j >> 4, c4 = (j & 15) * 4;
    const int l0base = blockIdx.y * RPB;

    for (int l0 = l0base; l0 < l0base + RPB; l0 += CHUNK) {
        __syncthreads();
        size_t off = ((size_t)(bb * L_ + l0 + r)) * D_ + hh * 64 + c4;
        float4 kk = *reinterpret_cast<const float4*>(Kp + off);
        kk.x *= SCALE; kk.y *= SCALE; kk.z *= SCALE; kk.w *= SCALE;
        *reinterpret_cast<float4*>(&sk[r][c4]) = kk;
        float4 vv = *reinterpret_cast<const float4*>(Vp + off);
        *reinterpret_cast<float4*>(&sv[r][c4]) = vv;
        float ss = kk.x * kk.x + kk.y * kk.y + kk.z * kk.z + kk.w * kk.w;
        ss += __shfl_xor_sync(0xffffffffu, ss, 8);
        ss += __shfl_xor_sync(0xffffffffu, ss, 4);
        ss += __shfl_xor_sync(0xffffffffu, ss, 2);
        ss += __shfl_xor_sync(0xffffffffu, ss, 1);
        if ((j & 15) == 0) sh[r] = -0.5f * ss;
        __syncthreads();

#pragma unroll
        for (int rr = 0; rr < CHUNK; ++rr) {
            const float4* skp = reinterpret_cast<const float4*>(sk[rr]);
            float p0 = 0.f, p1 = 0.f, p2 = 0.f, p3 = 0.f;
#pragma unroll
            for (int i = 0; i < 16; i += 4) {
                float4 a0 = skp[i], a1 = skp[i + 1], a2 = skp[i + 2], a3 = skp[i + 3];
                p0 += wj[4*i+ 0]*a0.x + wj[4*i+ 1]*a0.y + wj[4*i+ 2]*a0.z + wj[4*i+ 3]*a0.w;
                p1 += wj[4*i+ 4]*a1.x + wj[4*i+ 5]*a1.y + wj[4*i+ 6]*a1.z + wj[4*i+ 7]*a1.w;
                p2 += wj[4*i+ 8]*a2.x + wj[4*i+ 9]*a2.y + wj[4*i+10]*a2.z + wj[4*i+11]*a2.w;
                p3 += wj[4*i+12]*a3.x + wj[4*i+13]*a3.y + wj[4*i+14]*a3.z + wj[4*i+15]*a3.w;
            }
            float proj = (p0 + p1) + (p2 + p3);
            float kp = INVSQM * (__expf(sh[rr] + proj - stab) + CEPS);
            ksacc += kp;
            const float4* svp = reinterpret_cast<const float4*>(sv[rr]);
#pragma unroll
            for (int i = 0; i < 16; ++i) {
                float4 v4 = svp[i];
                kvacc[4 * i + 0] += kp * v4.x;
                kvacc[4 * i + 1] += kp * v4.y;
                kvacc[4 * i + 2] += kp * v4.z;
                kvacc[4 * i + 3] += kp * v4.w;
            }
        }
    }
    float* dst = g_kv + ((size_t)bh * M_ + j) * d_;
#pragma unroll
    for (int i = 0; i < 64; ++i) atomicAdd(dst + i, kvacc[i]);
    atomicAdd(g_ksum + bh * M_ + j, ksacc);
}

// ---------------------------------------------------------------------------
// Kernel 3: Q side. Stage kv (64KB) + ksum in smem per block.
// Phase 1: thread j computes q'_rj = c*(exp(proj)+eps)  (query stab cancels).
// Phase 2: thread (r, ct) computes out cols 4ct..4ct+3 of row r plus denom.
// ---------------------------------------------------------------------------
__global__ __launch_bounds__(256, 1) void phiq_kernel(
    const float* __restrict__ Qp, const float* __restrict__ Wp,
    float* __restrict__ Op) {
    extern __shared__ float sm[];
    float* s_kv = sm;                           // 256*64
    float* s_qp = sm + M_ * d_;                 // 16*260 (padded)
    float* s_q  = s_qp + CHUNK * QP_STRIDE;     // 16*64
    float* s_ks = s_q + CHUNK * d_;             // 256
    const int t = threadIdx.x;
    const int bh = blockIdx.x;
    const int bb = bh >> 4, hh = bh & 15;
    {
        const float4* gk = reinterpret_cast<const float4*>(g_kv + (size_t)bh * M_ * d_);
        float4* sk4 = reinterpret_cast<float4*>(s_kv);
#pragma unroll
        for (int i = 0; i < (M_ * d_ / 4) / 256; ++i) sk4[t + i * 256] = gk[t + i * 256];
        s_ks[t] = g_ksum[bh * M_ + t];
    }
    float wj[64];
    {
        const float4* w4 = reinterpret_cast<const float4*>(Wp + t * 64);
#pragma unroll
        for (int i = 0; i < 16; ++i) {
            float4 tw = w4[i];
            wj[4 * i] = tw.x; wj[4 * i + 1] = tw.y;
            wj[4 * i + 2] = tw.z; wj[4 * i + 3] = tw.w;
        }
    }
    const int r = t >> 4, c4 = (t & 15) * 4;
    const int l0base = blockIdx.y * RPB;

    for (int l0 = l0base; l0 < l0base + RPB; l0 += CHUNK) {
        __syncthreads();
        size_t off = ((size_t)(bb * L_ + l0 + r)) * D_ + hh * 64 + c4;
        float4 qq = *reinterpret_cast<const float4*>(Qp + off);
        qq.x *= SCALE; qq.y *= SCALE; qq.z *= SCALE; qq.w *= SCALE;
        *reinterpret_cast<float4*>(&s_q[r * 64 + c4]) = qq;
        __syncthreads();

#pragma unroll
        for (int rr = 0; rr < CHUNK; ++rr) {
            const float4* sqp = reinterpret_cast<const float4*>(s_q + rr * 64);
            float p0 = 0.f, p1 = 0.f, p2 = 0.f, p3 = 0.f;
#pragma unroll
            for (int i = 0; i < 16; i += 4) {
                float4 a0 = sqp[i], a1 = sqp[i + 1], a2 = sqp[i + 2], a3 = sqp[i + 3];
                p0 += wj[4*i+ 0]*a0.x + wj[4*i+ 1]*a0.y + wj[4*i+ 2]*a0.z + wj[4*i+ 3]*a0.w;
                p1 += wj[4*i+ 4]*a1.x + wj[4*i+ 5]*a1.y + wj[4*i+ 6]*a1.z + wj[4*i+ 7]*a1.w;
                p2 += wj[4*i+ 8]*a2.x + wj[4*i+ 9]*a2.y + wj[4*i+10]*a2.z + wj[4*i+11]*a2.w;
                p3 += wj[4*i+12]*a3.x + wj[4*i+13]*a3.y + wj[4*i+14]*a3.z + wj[4*i+15]*a3.w;
            }
            float proj = (p0 + p1) + (p2 + p3);
            s_qp[rr * QP_STRIDE + t] = INVSQM * (__expf(proj) + CEPS);
        }
        __syncthreads();

        float a0 = 0.f, a1 = 0.f, a2 = 0.f, a3 = 0.f, den = 0.f;
        const float* qpr = s_qp + r * QP_STRIDE;
#pragma unroll 8
        for (int j2 = 0; j2 < M_; ++j2) {
            float qv = qpr[j2];
            float4 kv4 = *reinterpret_cast<const float4*>(s_kv + j2 * 64 + c4);
            a0 += qv * kv4.x;
            a1 += qv * kv4.y;
            a2 += qv * kv4.z;
            a3 += qv * kv4.w;
            den += qv * s_ks[j2];
        }
        if (fabsf(den) <= CEPS) den += 2.f * CEPS;
        float inv = 1.f / den;
        float4 o4 = make_float4(a0 * inv, a1 * inv, a2 * inv, a3 * inv);
        *reinterpret_cast<float4*>(Op + off) = o4;
    }
}

// ---------------------------------------------------------------------------
extern "C" void kernel_launch(void* const* d_in, const int* in_sizes, int n_in,
                              void* d_out, int out_size) {
    const float* q = (const float*)d_in[0];
    const float* k = (const float*)d_in[1];
    const float* v = (const float*)d_in[2];
    const float* w = (const float*)d_in[3];
    float* out = (float*)d_out;

    cudaFuncSetAttribute(phiq_kernel, cudaFuncAttributeMaxDynamicSharedMemorySize,
                         QSMEM_BYTES);

    zero_kernel<<<2048, 256>>>();
    min_kernel<<<1024, 256>>>(k);                       // 262144 chunks
    phik_kernel<<<dim3(B_ * H_, SPLIT), 256>>>(k, v, w);
    phiq_kernel<<<dim3(B_ * H_, SPLIT), 256, QSMEM_BYTES>>>(q, w, out);
}

// round 2
// speedup vs baseline: 1.6098x; 1.6098x over previous
#include <cuda_runtime.h>

// FAVOR+ attention, fp32 baseline.
// B=4, L=4096, D=1024, H=16 heads of d=64, m=256 features.
// Pipeline: zero scratch -> global min ||k_chunk||^2 -> K-side (phi_k fused with
// kv/ksum accumulation) -> Q-side (phi_q fused with output GEMM + denom).

namespace {
constexpr int B_ = 4;
constexpr int L_ = 4096;
constexpr int D_ = 1024;
constexpr int H_ = 16;
constexpr int d_ = 64;
constexpr int M_ = 256;
constexpr int SPLIT = 8;
constexpr int RPB = L_ / SPLIT;   // 512 rows per block
constexpr int CHUNK = 16;
constexpr float SCALE = 0.17677669529663687f;  // 1024^-0.25
constexpr float CEPS = 1e-4f;
constexpr float INVSQM = 0.0625f;              // 256^-0.5
constexpr int QP_STRIDE = 260;                 // padded to dodge bank conflicts
constexpr int QSMEM_FLOATS = M_ * d_ + CHUNK * QP_STRIDE + CHUNK * d_ + M_;
constexpr int QSMEM_BYTES = QSMEM_FLOATS * 4;  // 87296
}

__device__ float g_kv[B_ * H_ * M_ * d_];   // 16 MB scratch
__device__ float g_ksum[B_ * H_ * M_];
__device__ unsigned int g_min_ss;

// ---------------------------------------------------------------------------
// Kernel 0: re-zero scratch + init min (must run every launch: graph replays)
// ---------------------------------------------------------------------------
__global__ void zero_kernel() {
    size_t tid = (size_t)blockIdx.x * blockDim.x + threadIdx.x;
    size_t stride = (size_t)gridDim.x * blockDim.x;
    constexpr size_t nkv = (size_t)B_ * H_ * M_ * d_;
    for (size_t i = tid; i < nkv; i += stride) g_kv[i] = 0.f;
    constexpr size_t nks = (size_t)B_ * H_ * M_;
    for (size_t i = tid; i < nks; i += stride) g_ksum[i] = 0.f;
    if (tid == 0) g_min_ss = 0x7F800000u;  // +inf
}

// ---------------------------------------------------------------------------
// Kernel 1: global min over all (b,h,l) of ||k_head_row||^2 (raw, unscaled).
// stab = -0.5 * SCALE^2 * min_ss  ==  max over all h of -0.5*||k*scale||^2
// ---------------------------------------------------------------------------
__global__ __launch_bounds__(256) void min_kernel(const float* __restrict__ Kp) {
    int t = threadIdx.x;
    float mn = 3.4028235e38f;
#pragma unroll
    for (int it = 0; it < 16; ++it) {
        size_t ch = (size_t)blockIdx.x * 256 + it * 16 + (t >> 4);
        float4 v4 = *reinterpret_cast<const float4*>(Kp + ch * 64 + (t & 15) * 4);
        float ss = v4.x * v4.x + v4.y * v4.y + v4.z * v4.z + v4.w * v4.w;
        ss += __shfl_xor_sync(0xffffffffu, ss, 8);
        ss += __shfl_xor_sync(0xffffffffu, ss, 4);
        ss += __shfl_xor_sync(0xffffffffu, ss, 2);
        ss += __shfl_xor_sync(0xffffffffu, ss, 1);
        mn = fminf(mn, ss);
    }
    mn = fminf(mn, __shfl_xor_sync(0xffffffffu, mn, 16));
    __shared__ float wmin[8];
    if ((t & 31) == 0) wmin[t >> 5] = mn;
    __syncthreads();
    if (t < 8) {
        float m2 = wmin[t];
        m2 = fminf(m2, __shfl_xor_sync(0xffu, m2, 4));
        m2 = fminf(m2, __shfl_xor_sync(0xffu, m2, 2));
        m2 = fminf(m2, __shfl_xor_sync(0xffu, m2, 1));
        if (t == 0) atomicMin(&g_min_ss, __float_as_uint(m2));
    }
}

// ---------------------------------------------------------------------------
// Kernel 2: K side. Thread j owns W row j (regs) and kv row j (regs).
// Per 16-row chunk: stage scaled k rows + v rows in smem (broadcast reads),
// compute proj_j per row, k' = c*(exp(h + proj - stab) + eps),
// rank-1 accumulate kv[j][:] += k' * v_row.  Atomic writeback per block.
// ---------------------------------------------------------------------------
__global__ __launch_bounds__(256, 1) void phik_kernel(
    const float* __restrict__ Kp, const float* __restrict__ Vp,
    const float* __restrict__ Wp) {
    const int j = threadIdx.x;
    const int bh = blockIdx.x;
    const int bb = bh >> 4, hh = bh & 15;
    float wj[64];
    {
        const float4* w4 = reinterpret_cast<const float4*>(Wp + j * 64);
#pragma unroll
        for (int i = 0; i < 16; ++i) {
            float4 tw = w4[i];
            wj[4 * i] = tw.x; wj[4 * i + 1] = tw.y;
            wj[4 * i + 2] = tw.z; wj[4 * i + 3] = tw.w;
        }
    }
    const float stab = -0.5f * SCALE * SCALE * __uint_as_float(g_min_ss);
    float kvacc[64];
#pragma unroll
    for (int i = 0; i < 64; ++i) kvacc[i] = 0.f;
    float ksacc = 0.f;

    __shared__ float sk[CHUNK][64];
    __shared__ float sv[CHUNK][64];
    __shared__ float sh[CHUNK];
    const int r = j >> 4, c4 = (j & 15) * 4;
    const int l0base = blockIdx.y * RPB;

    for (int l0 = l0base; l0 < l0base + RPB; l0 += CHUNK) {
        __syncthreads();
        size_t off = ((size_t)(bb * L_ + l0 + r)) * D_ + hh * 64 + c4;
        float4 kk = *reinterpret_cast<const float4*>(Kp + off);
        kk.x *= SCALE; kk.y *= SCALE; kk.z *= SCALE; kk.w *= SCALE;
        *reinterpret_cast<float4*>(&sk[r][c4]) = kk;
        float4 vv = *reinterpret_cast<const float4*>(Vp + off);
        *reinterpret_cast<float4*>(&sv[r][c4]) = vv;
        float ss = kk.x * kk.x + kk.y * kk.y + kk.z * kk.z + kk.w * kk.w;
        ss += __shfl_xor_sync(0xffffffffu, ss, 8);
        ss += __shfl_xor_sync(0xffffffffu, ss, 4);
        ss += __shfl_xor_sync(0xffffffffu, ss, 2);
        ss += __shfl_xor_sync(0xffffffffu, ss, 1);
        if ((j & 15) == 0) sh[r] = -0.5f * ss;
        __syncthreads();

#pragma unroll
        for (int rr = 0; rr < CHUNK; ++rr) {
            const float4* skp = reinterpret_cast<const float4*>(sk[rr]);
            float p0 = 0.f, p1 = 0.f, p2 = 0.f, p3 = 0.f;
#pragma unroll
            for (int i = 0; i < 16; i += 4) {
                float4 a0 = skp[i], a1 = skp[i + 1], a2 = skp[i + 2], a3 = skp[i + 3];
                p0 += wj[4*i+ 0]*a0.x + wj[4*i+ 1]*a0.y + wj[4*i+ 2]*a0.z + wj[4*i+ 3]*a0.w;
                p1 += wj[4*i+ 4]*a1.x + wj[4*i+ 5]*a1.y + wj[4*i+ 6]*a1.z + wj[4*i+ 7]*a1.w;
                p2 += wj[4*i+ 8]*a2.x + wj[4*i+ 9]*a2.y + wj[4*i+10]*a2.z + wj[4*i+11]*a2.w;
                p3 += wj[4*i+12]*a3.x + wj[4*i+13]*a3.y + wj[4*i+14]*a3.z + wj[4*i+15]*a3.w;
            }
            float proj = (p0 + p1) + (p2 + p3);
            float kp = INVSQM * (__expf(sh[rr] + proj - stab) + CEPS);
            ksacc += kp;
            const float4* svp = reinterpret_cast<const float4*>(sv[rr]);
#pragma unroll
            for (int i = 0; i < 16; ++i) {
                float4 v4 = svp[i];
                kvacc[4 * i + 0] += kp * v4.x;
                kvacc[4 * i + 1] += kp * v4.y;
                kvacc[4 * i + 2] += kp * v4.z;
                kvacc[4 * i + 3] += kp * v4.w;
            }
        }
    }
    float* dst = g_kv + ((size_t)bh * M_ + j) * d_;
#pragma unroll
    for (int i = 0; i < 64; ++i) atomicAdd(dst + i, kvacc[i]);
    atomicAdd(g_ksum + bh * M_ + j, ksacc);
}

// ---------------------------------------------------------------------------
// Kernel 3: Q side. Stage kv (64KB) + ksum in smem per block.
// Phase 1: thread j computes q'_rj = c*(exp(proj)+eps)  (query stab cancels).
// Phase 2: thread (r, ct) computes out cols 4ct..4ct+3 of row r plus denom.
// ---------------------------------------------------------------------------
__global__ __launch_bounds__(256, 1) void phiq_kernel(
    const float* __restrict__ Qp, const float* __restrict__ Wp,
    float* __restrict__ Op) {
    extern __shared__ float sm[];
    float* s_kv = sm;                           // 256*64
    float* s_qp = sm + M_ * d_;                 // 16*260 (padded)
    float* s_q  = s_qp + CHUNK * QP_STRIDE;     // 16*64
    float* s_ks = s_q + CHUNK * d_;             // 256
    const int t = threadIdx.x;
    const int bh = blockIdx.x;
    const int bb = bh >> 4, hh = bh & 15;
    {
        const float4* gk = reinterpret_cast<const float4*>(g_kv + (size_t)bh * M_ * d_);
        float4* sk4 = reinterpret_cast<float4*>(s_kv);
#pragma unroll
        for (int i = 0; i < (M_ * d_ / 4) / 256; ++i) sk4[t + i * 256] = gk[t + i * 256];
        s_ks[t] = g_ksum[bh * M_ + t];
    }
    float wj[64];
    {
        const float4* w4 = reinterpret_cast<const float4*>(Wp + t * 64);
#pragma unroll
        for (int i = 0; i < 16; ++i) {
            float4 tw = w4[i];
            wj[4 * i] = tw.x; wj[4 * i + 1] = tw.y;
            wj[4 * i + 2] = tw.z; wj[4 * i + 3] = tw.w;
        }
    }
    const int r = t >> 4, c4 = (t & 15) * 4;
    const int l0base = blockIdx.y * RPB;

    for (int l0 = l0base; l0 < l0base + RPB; l0 += CHUNK) {
        __syncthreads();
        size_t off = ((size_t)(bb * L_ + l0 + r)) * D_ + hh * 64 + c4;
        float4 qq = *reinterpret_cast<const float4*>(Qp + off);
        qq.x *= SCALE; qq.y *= SCALE; qq.z *= SCALE; qq.w *= SCALE;
        *reinterpret_cast<float4*>(&s_q[r * 64 + c4]) = qq;
        __syncthreads();

#pragma unroll
        for (int rr = 0; rr < CHUNK; ++rr) {
            const float4* sqp = reinterpret_cast<const float4*>(s_q + rr * 64);
            float p0 = 0.f, p1 = 0.f, p2 = 0.f, p3 = 0.f;
#pragma unroll
            for (int i = 0; i < 16; i += 4) {
                float4 a0 = sqp[i], a1 = sqp[i + 1], a2 = sqp[i + 2], a3 = sqp[i + 3];
                p0 += wj[4*i+ 0]*a0.x + wj[4*i+ 1]*a0.y + wj[4*i+ 2]*a0.z + wj[4*i+ 3]*a0.w;
                p1 += wj[4*i+ 4]*a1.x + wj[4*i+ 5]*a1.y + wj[4*i+ 6]*a1.z + wj[4*i+ 7]*a1.w;
                p2 += wj[4*i+ 8]*a2.x + wj[4*i+ 9]*a2.y + wj[4*i+10]*a2.z + wj[4*i+11]*a2.w;
                p3 += wj[4*i+12]*a3.x + wj[4*i+13]*a3.y + wj[4*i+14]*a3.z + wj[4*i+15]*a3.w;
            }
            float proj = (p0 + p1) + (p2 + p3);
            s_qp[rr * QP_STRIDE + t] = INVSQM * (__expf(proj) + CEPS);
        }
        __syncthreads();

        float a0 = 0.f, a1 = 0.f, a2 = 0.f, a3 = 0.f, den = 0.f;
        const float* qpr = s_qp + r * QP_STRIDE;
#pragma unroll 8
        for (int j2 = 0; j2 < M_; ++j2) {
            float qv = qpr[j2];
            float4 kv4 = *reinterpret_cast<const float4*>(s_kv + j2 * 64 + c4);
            a0 += qv * kv4.x;
            a1 += qv * kv4.y;
            a2 += qv * kv4.z;
            a3 += qv * kv4.w;
            den += qv * s_ks[j2];
        }
        if (fabsf(den) <= CEPS) den += 2.f * CEPS;
        float inv = 1.f / den;
        float4 o4 = make_float4(a0 * inv, a1 * inv, a2 * inv, a3 * inv);
        *reinterpret_cast<float4*>(Op + off) = o4;
    }
}

// ---------------------------------------------------------------------------
extern "C" void kernel_launch(void* const* d_in, const int* in_sizes, int n_in,
                              void* d_out, int out_size) {
    const float* q = (const float*)d_in[0];
    const float* k = (const float*)d_in[1];
    const float* v = (const float*)d_in[2];
    const float* w = (const float*)d_in[3];
    float* out = (float*)d_out;

    cudaFuncSetAttribute(phiq_kernel, cudaFuncAttributeMaxDynamicSharedMemorySize,
                         QSMEM_BYTES);

    zero_kernel<<<2048, 256>>>();
    min_kernel<<<1024, 256>>>(k);                       // 262144 chunks
    phik_kernel<<<dim3(B_ * H_, SPLIT), 256>>>(k, v, w);
    phiq_kernel<<<dim3(B_ * H_, SPLIT), 256, QSMEM_BYTES>>>(q, w, out);
}

// round 4
// speedup vs baseline: 4.9855x; 3.0969x over previous
#include <cuda_runtime.h>
#include <cstdint>

// FAVOR+ attention via legacy mma.sync tf32 (compiles for base sm_103 target).
// B=4, L=4096, D=1024, H=16 x d=64, m=256 features.

namespace {
constexpr int L_ = 4096, D_ = 1024;
constexpr float SCALE = 0.17677669529663687f, SC2 = SCALE * SCALE;
constexpr float CEPS = 1e-4f, INVSQM = 0.0625f;
// K-phase smem layout (float offsets)
constexpr int KW = 0;              // W   [256][68]
constexpr int KX = 17408;          // K   [128][68]
constexpr int KV = 26112;          // V^T [72][132]  (row 64 = ones)
constexpr int KP = 35616;          // k'  [128 f][132 l]
constexpr int KH = 52512;          // ssq [128]
constexpr int KFL = 52640;         // 210560 B
// Q-phase smem layout
constexpr int QW = 0;              // W    [256][68]
constexpr int QP = 17408;          // q'   [64][260]  (Q tile [64][68] overlaid)
constexpr int QKV = 34048;         // KV^T [72][260]
constexpr int QDEN = 52768;        // den  [64]
constexpr int QFL = 52832;         // 211328 B
}

__device__ float g_kv[64 * 256 * 72];   // [bh][f][d'(64=ksum)]
__device__ unsigned g_min_ss;

__device__ __forceinline__ uint32_t cvt_tf32(float x) {
    uint32_t r;
    asm("cvt.rna.tf32.f32 %0, %1;" : "=r"(r) : "f"(x));
    return r;
}
__device__ __forceinline__ void mma8(float* c, const uint32_t* a, const uint32_t* b) {
    asm volatile(
        "mma.sync.aligned.m16n8k8.row.col.f32.tf32.tf32.f32 "
        "{%0,%1,%2,%3},{%4,%5,%6,%7},{%8,%9},{%0,%1,%2,%3};"
        : "+f"(c[0]), "+f"(c[1]), "+f"(c[2]), "+f"(c[3])
        : "r"(a[0]), "r"(a[1]), "r"(a[2]), "r"(a[3]), "r"(b[0]), "r"(b[1]));
}

// ---------------------------------------------------------------------------
__global__ void zero_kernel() {
    size_t tid = (size_t)blockIdx.x * blockDim.x + threadIdx.x;
    size_t stride = (size_t)gridDim.x * blockDim.x;
    constexpr size_t n = (size_t)64 * 256 * 72;
    for (size_t i = tid; i < n; i += stride) g_kv[i] = 0.f;
    if (tid == 0) g_min_ss = 0x7F800000u;
}

__global__ __launch_bounds__(256) void min_kernel(const float* __restrict__ Kp) {
    int t = threadIdx.x;
    float mn = 3.4028235e38f;
#pragma unroll
    for (int it = 0; it < 16; ++it) {
        size_t ch = (size_t)blockIdx.x * 256 + it * 16 + (t >> 4);
        float4 v4 = *reinterpret_cast<const float4*>(Kp + ch * 64 + (t & 15) * 4);
        float ss = v4.x * v4.x + v4.y * v4.y + v4.z * v4.z + v4.w * v4.w;
        ss += __shfl_xor_sync(~0u, ss, 8); ss += __shfl_xor_sync(~0u, ss, 4);
        ss += __shfl_xor_sync(~0u, ss, 2); ss += __shfl_xor_sync(~0u, ss, 1);
        mn = fminf(mn, ss);
    }
    mn = fminf(mn, __shfl_xor_sync(~0u, mn, 16));
    __shared__ float wmin[8];
    if ((t & 31) == 0) wmin[t >> 5] = mn;
    __syncthreads();
    if (t < 8) {
        float m2 = wmin[t];
        m2 = fminf(m2, __shfl_xor_sync(0xffu, m2, 4));
        m2 = fminf(m2, __shfl_xor_sync(0xffu, m2, 2));
        m2 = fminf(m2, __shfl_xor_sync(0xffu, m2, 1));
        if (t == 0) atomicMin(&g_min_ss, __float_as_uint(m2));
    }
}

// ---------------------------------------------------------------------------
// K phase: per 128-row tile: S = K x W^T (tf32 mma), epilogue exp -> k' in
// smem [f][l], then KV[f, 72] += k'^T x Vaug with KV acc in registers.
// ---------------------------------------------------------------------------
__global__ __launch_bounds__(256, 1) void favor_k(
    const float* __restrict__ K_, const float* __restrict__ V_,
    const float* __restrict__ W_) {
    extern __shared__ float s[];
    const int t = threadIdx.x, w = t >> 5;
    const int qrow = (t & 31) >> 2, qcol = t & 3;
    const int bh = blockIdx.x, bb = bh >> 4, hh = bh & 15;
#pragma unroll
    for (int i = 0; i < 16; ++i) {
        int idx = t + i * 256, f = idx >> 4, c4 = idx & 15;
        *reinterpret_cast<float4*>(s + KW + f * 68 + c4 * 4) =
            *reinterpret_cast<const float4*>(W_ + f * 64 + c4 * 4);
    }
    if (t < 128) {
#pragma unroll
        for (int r = 64; r < 72; ++r) s[KV + r * 132 + t] = (r == 64) ? 1.f : 0.f;
    }
    const float stab = -0.5f * SC2 * __uint_as_float(g_min_ss);
    float kvacc[2][9][4];
#pragma unroll
    for (int h = 0; h < 2; ++h)
#pragma unroll
        for (int ni = 0; ni < 9; ++ni)
#pragma unroll
            for (int j = 0; j < 4; ++j) kvacc[h][ni][j] = 0.f;
    __syncthreads();

    const int mbase = (w >> 1) * 32, nb = (w & 1) * 64;

    for (int ti = 0; ti < 8; ++ti) {
        const int l0 = ((int)blockIdx.y * 8 + ti) * 128;
        if (t < 128) s[KH + t] = 0.f;
        __syncthreads();
#pragma unroll
        for (int i = 0; i < 8; ++i) {
            int idx = t + i * 256, l = idx >> 4, c4 = idx & 15;
            size_t off = ((size_t)(bb * L_ + l0 + l)) * D_ + hh * 64 + c4 * 4;
            float4 kk = *reinterpret_cast<const float4*>(K_ + off);
            *reinterpret_cast<float4*>(s + KX + l * 68 + c4 * 4) = kk;
            atomicAdd(s + KH + l, kk.x * kk.x + kk.y * kk.y + kk.z * kk.z + kk.w * kk.w);
            float4 vv = *reinterpret_cast<const float4*>(V_ + off);
            int d0 = c4 * 4;
            s[KV + (d0 + 0) * 132 + l] = vv.x;
            s[KV + (d0 + 1) * 132 + l] = vv.y;
            s[KV + (d0 + 2) * 132 + l] = vv.z;
            s[KV + (d0 + 3) * 132 + l] = vv.w;
        }
        __syncthreads();

#pragma unroll
        for (int h = 0; h < 2; ++h) {
            // ---- GEMM1: S[128, f-half 128] ----
            float c[2][8][4];
#pragma unroll
            for (int mi = 0; mi < 2; ++mi)
#pragma unroll
                for (int ni = 0; ni < 8; ++ni)
#pragma unroll
                    for (int j = 0; j < 4; ++j) c[mi][ni][j] = 0.f;
#pragma unroll
            for (int ks = 0; ks < 8; ++ks) {
                uint32_t a[2][4];
#pragma unroll
                for (int mi = 0; mi < 2; ++mi) {
                    const float* ap = s + KX + (mbase + mi * 16 + qrow) * 68 + ks * 8 + qcol;
                    a[mi][0] = cvt_tf32(ap[0]);
                    a[mi][1] = cvt_tf32(ap[8 * 68]);
                    a[mi][2] = cvt_tf32(ap[4]);
                    a[mi][3] = cvt_tf32(ap[8 * 68 + 4]);
                }
#pragma unroll
                for (int ni = 0; ni < 8; ++ni) {
                    const float* bp = s + KW + (h * 128 + nb + ni * 8 + qrow) * 68 + ks * 8 + qcol;
                    uint32_t b[2] = {cvt_tf32(bp[0]), cvt_tf32(bp[4])};
                    mma8(c[0][ni], a[0], b);
                    mma8(c[1][ni], a[1], b);
                }
            }
            // ---- epilogue: k' -> sKP[f][l] ----
#pragma unroll
            for (int mi = 0; mi < 2; ++mi) {
                int r0 = mbase + mi * 16 + qrow;
                float eb0 = -0.5f * SC2 * s[KH + r0] - stab;
                float eb1 = -0.5f * SC2 * s[KH + r0 + 8] - stab;
#pragma unroll
                for (int ni = 0; ni < 8; ++ni) {
                    int fh = nb + ni * 8 + qcol * 2;
                    s[KP + fh * 132 + r0] =
                        INVSQM * (__expf(fmaf(SCALE, c[mi][ni][0], eb0)) + CEPS);
                    s[KP + (fh + 1) * 132 + r0] =
                        INVSQM * (__expf(fmaf(SCALE, c[mi][ni][1], eb0)) + CEPS);
                    s[KP + fh * 132 + r0 + 8] =
                        INVSQM * (__expf(fmaf(SCALE, c[mi][ni][2], eb1)) + CEPS);
                    s[KP + (fh + 1) * 132 + r0 + 8] =
                        INVSQM * (__expf(fmaf(SCALE, c[mi][ni][3], eb1)) + CEPS);
                }
            }
            __syncthreads();
            // ---- GEMM2: KV[f 16/warp, 72] += k'^T x Vaug ----
#pragma unroll
            for (int ks = 0; ks < 16; ++ks) {
                uint32_t a[4];
                const float* ap = s + KP + (w * 16 + qrow) * 132 + ks * 8 + qcol;
                a[0] = cvt_tf32(ap[0]);
                a[1] = cvt_tf32(ap[8 * 132]);
                a[2] = cvt_tf32(ap[4]);
                a[3] = cvt_tf32(ap[8 * 132 + 4]);
#pragma unroll
                for (int ni = 0; ni < 9; ++ni) {
                    const float* bp = s + KV + (ni * 8 + qrow) * 132 + ks * 8 + qcol;
                    uint32_t b[2] = {cvt_tf32(bp[0]), cvt_tf32(bp[4])};
                    mma8(kvacc[h][ni], a, b);
                }
            }
            __syncthreads();
        }
    }
    // writeback
    float* g = g_kv + (size_t)bh * 256 * 72;
#pragma unroll
    for (int h = 0; h < 2; ++h)
#pragma unroll
        for (int ni = 0; ni < 9; ++ni) {
            int f0 = h * 128 + w * 16 + qrow, d0 = ni * 8 + qcol * 2;
            atomicAdd(g + f0 * 72 + d0, kvacc[h][ni][0]);
            atomicAdd(g + f0 * 72 + d0 + 1, kvacc[h][ni][1]);
            atomicAdd(g + (f0 + 8) * 72 + d0, kvacc[h][ni][2]);
            atomicAdd(g + (f0 + 8) * 72 + d0 + 1, kvacc[h][ni][3]);
        }
}

// ---------------------------------------------------------------------------
// Q phase: per 64-row tile: S = Q x W^T, q' = c*(exp(SCALE*S)+eps) -> smem,
// out[64, 72] = q' x KV^T (col 64 = denominator), divide, store.
// ---------------------------------------------------------------------------
__global__ __launch_bounds__(256, 1) void favor_q(
    const float* __restrict__ Q_, const float* __restrict__ W_,
    float* __restrict__ O_) {
    extern __shared__ float s[];
    const int t = threadIdx.x, w = t >> 5;
    const int qrow = (t & 31) >> 2, qcol = t & 3;
    const int bh = blockIdx.x, bb = bh >> 4, hh = bh & 15;
#pragma unroll
    for (int i = 0; i < 16; ++i) {
        int idx = t + i * 256, f = idx >> 4, c4 = idx & 15;
        *reinterpret_cast<float4*>(s + QW + f * 68 + c4 * 4) =
            *reinterpret_cast<const float4*>(W_ + f * 64 + c4 * 4);
    }
    {
        const float* g = g_kv + (size_t)bh * 256 * 72;
        for (int d = 0; d < 72; ++d) s[QKV + d * 260 + t] = g[t * 72 + d];
    }
    __syncthreads();

    const int mbase = (w >> 2) * 32, nb = (w & 3) * 64;   // GEMM1 mapping
    const int lb = (w >> 1) * 16, nh = w & 1;             // GEMM3 mapping
    const int nf = nh ? 4 : 5, nb3 = nh ? 40 : 0;

    for (int ti = 0; ti < 16; ++ti) {
        const int l0 = ((int)blockIdx.y * 16 + ti) * 64;
#pragma unroll
        for (int i = 0; i < 4; ++i) {
            int idx = t + i * 256, l = idx >> 4, c4 = idx & 15;
            size_t off = ((size_t)(bb * L_ + l0 + l)) * D_ + hh * 64 + c4 * 4;
            *reinterpret_cast<float4*>(s + QP + l * 68 + c4 * 4) =
                *reinterpret_cast<const float4*>(Q_ + off);
        }
        __syncthreads();
        // ---- GEMM1: S[64, 256] ----
        float c[2][8][4];
#pragma unroll
        for (int mi = 0; mi < 2; ++mi)
#pragma unroll
            for (int ni = 0; ni < 8; ++ni)
#pragma unroll
                for (int j = 0; j < 4; ++j) c[mi][ni][j] = 0.f;
#pragma unroll
        for (int ks = 0; ks < 8; ++ks) {
            uint32_t a[2][4];
#pragma unroll
            for (int mi = 0; mi < 2; ++mi) {
                const float* ap = s + QP + (mbase + mi * 16 + qrow) * 68 + ks * 8 + qcol;
                a[mi][0] = cvt_tf32(ap[0]);
                a[mi][1] = cvt_tf32(ap[8 * 68]);
                a[mi][2] = cvt_tf32(ap[4]);
                a[mi][3] = cvt_tf32(ap[8 * 68 + 4]);
            }
#pragma unroll
            for (int ni = 0; ni < 8; ++ni) {
                const float* bp = s + QW + (nb + ni * 8 + qrow) * 68 + ks * 8 + qcol;
                uint32_t b[2] = {cvt_tf32(bp[0]), cvt_tf32(bp[4])};
                mma8(c[0][ni], a[0], b);
                mma8(c[1][ni], a[1], b);
            }
        }
        __syncthreads();   // before q' overwrites the Q-tile region
        // ---- epilogue: q' -> sQP[l][f] ----
#pragma unroll
        for (int mi = 0; mi < 2; ++mi) {
            int r0 = mbase + mi * 16 + qrow;
#pragma unroll
            for (int ni = 0; ni < 8; ++ni) {
                int f = nb + ni * 8 + qcol * 2;
                s[QP + r0 * 260 + f] = INVSQM * (__expf(SCALE * c[mi][ni][0]) + CEPS);
                s[QP + r0 * 260 + f + 1] = INVSQM * (__expf(SCALE * c[mi][ni][1]) + CEPS);
                s[QP + (r0 + 8) * 260 + f] = INVSQM * (__expf(SCALE * c[mi][ni][2]) + CEPS);
                s[QP + (r0 + 8) * 260 + f + 1] = INVSQM * (__expf(SCALE * c[mi][ni][3]) + CEPS);
            }
        }
        __syncthreads();
        // ---- GEMM3: out[64, 72] = q' x KV^T ----
        float o[5][4];
#pragma unroll
        for (int ni = 0; ni < 5; ++ni)
#pragma unroll
            for (int j = 0; j < 4; ++j) o[ni][j] = 0.f;
#pragma unroll
        for (int ks = 0; ks < 32; ++ks) {
            uint32_t a[4];
            const float* ap = s + QP + (lb + qrow) * 260 + ks * 8 + qcol;
            a[0] = cvt_tf32(ap[0]);
            a[1] = cvt_tf32(ap[8 * 260]);
            a[2] = cvt_tf32(ap[4]);
            a[3] = cvt_tf32(ap[8 * 260 + 4]);
#pragma unroll
            for (int ni = 0; ni < 5; ++ni)
                if (ni < nf) {
                    const float* bp = s + QKV + (nb3 + ni * 8 + qrow) * 260 + ks * 8 + qcol;
                    uint32_t b[2] = {cvt_tf32(bp[0]), cvt_tf32(bp[4])};
                    mma8(o[ni], a, b);
                }
        }
        if (nh == 1 && qcol == 0) {        // col 64 = denominator
            s[QDEN + lb + qrow] = o[3][0];
            s[QDEN + lb + qrow + 8] = o[3][2];
        }
        __syncthreads();
        float dv0 = s[QDEN + lb + qrow], dv1 = s[QDEN + lb + qrow + 8];
        if (fabsf(dv0) <= CEPS) dv0 += 2.f * CEPS;
        if (fabsf(dv1) <= CEPS) dv1 += 2.f * CEPS;
        float inv0 = 1.f / dv0, inv1 = 1.f / dv1;
        float* op0 = O_ + ((size_t)(bb * L_ + l0 + lb + qrow)) * D_ + hh * 64;
        float* op1 = op0 + 8 * D_;
#pragma unroll
        for (int ni = 0; ni < 5; ++ni)
            if (ni < nf) {
                int col = nb3 + ni * 8 + qcol * 2;
                if (col < 64) {
                    float2 v0 = make_float2(o[ni][0] * inv0, o[ni][1] * inv0);
                    float2 v1 = make_float2(o[ni][2] * inv1, o[ni][3] * inv1);
                    *reinterpret_cast<float2*>(op0 + col) = v0;
                    *reinterpret_cast<float2*>(op1 + col) = v1;
                }
            }
        __syncthreads();
    }
}

// ---------------------------------------------------------------------------
extern "C" void kernel_launch(void* const* d_in, const int* in_sizes, int n_in,
                              void* d_out, int out_size) {
    const float* q = (const float*)d_in[0];
    const float* k = (const float*)d_in[1];
    const float* v = (const float*)d_in[2];
    const float* w = (const float*)d_in[3];
    float* out = (float*)d_out;

    cudaFuncSetAttribute(favor_k, cudaFuncAttributeMaxDynamicSharedMemorySize, KFL * 4);
    cudaFuncSetAttribute(favor_q, cudaFuncAttributeMaxDynamicSharedMemorySize, QFL * 4);

    zero_kernel<<<512, 256>>>();
    min_kernel<<<1024, 256>>>(k);
    favor_k<<<dim3(64, 4), 256, KFL * 4>>>(k, v, w);
    favor_q<<<dim3(64, 4), 256, QFL * 4>>>(q, w, out);
}